// round 12
// baseline (speedup 1.0000x reference)
#include <cuda_runtime.h>
#include <cuda_bf16.h>
#include <mma.h>
#include <math.h>
#include <stdint.h>

using namespace nvcuda;
typedef __nv_bfloat16 bf16;
static constexpr int SQ = 2048, DM = 1024, NH = 16;
static constexpr long long SS = (long long)SQ * SQ;

__device__ float g_rel[SQ*DM], g_q[SQ*DM], g_k[SQ*DM];
__device__ float g_qrel[SQ*DM], g_vt[DM*SQ], g_ctx[SQ*DM];
__device__ unsigned int g_headmax[NH];

// ---------------- small kernels ----------------
__global__ void relenc_kernel() {
    int idx = blockIdx.x * blockDim.x + threadIdx.x;
    if (idx < NH) g_headmax[idx] = 0u;
    if (idx >= SQ * DM) return;
    int f = idx >> 10, c = idx & (DM - 1);
    int p = SQ - 1 - f, i2 = c & ~1;
    double dv = exp(-((double)i2 / (double)DM) * log(10000.0));
    float angf = (float)p * (float)dv;
    double a = (double)angf;
    g_rel[idx] = (float)((c & 1) ? cos(a) : sin(a));
}

// split one float4 into hi/lo bf16 quads; store at pitch-40 layout
__device__ __forceinline__ void st_split(bf16 (*H)[40], bf16 (*L)[40],
    int idx, float4 x, const float* __restrict__ bias, int kcol)
{
    float xv[4] = {x.x, x.y, x.z, x.w};
    if (bias) {
        #pragma unroll
        for (int e = 0; e < 4; e++) xv[e] += bias[kcol + e];
    }
    __align__(8) bf16 h[4], l[4];
    #pragma unroll
    for (int e = 0; e < 4; e++) {
        h[e] = __float2bfloat16(xv[e]);
        l[e] = __float2bfloat16(xv[e] - __bfloat162float(h[e]));
    }
    int r = idx >> 3, c = (idx & 7) * 4;
    *(uint2*)&H[r][c] = *(uint2*)h;
    *(uint2*)&L[r][c] = *(uint2*)l;
}

// ---------------- split-bf16 WMMA GEMM body: 512 threads, 16 warps --------
// Warp grid NWM x NWN (NWN = BN/32), warp tile 32x32 (FM=2 frag rows).
// mode 0: plain store; 2: gelu; 3: transposed store C[DM][SQ] (for vt).
template <int BM, int BN>
__device__ __forceinline__ void wgemm_body(char* sm,
    const float* __restrict__ A, const float* __restrict__ B, float* __restrict__ C,
    int K, int lda, int ldb, int ldc, const float* __restrict__ bp,
    int m0, int n0, int mode)
{
    constexpr int NWN = BN / 32;          // 4 or 2
    constexpr int NWM = 16 / NWN;         // 4 or 8
    constexpr int FM  = BM / (NWM * 16);  // 2
    constexpr int TA  = BM * 40 * 2;
    constexpr int TB  = BN * 40 * 2;
    constexpr int STAGE = 2 * TA + 2 * TB;
    constexpr int NA4 = BM / 64;          // float4 per thread, A tile
    constexpr int NB4 = BN / 64 > 0 ? BN / 64 : 1;

    int t = threadIdx.x, w = t >> 5, lane = t & 31;
    int wm = w / NWN, wn = w % NWN;
    const float* Ap = A + (long long)m0 * lda;
    const float* Bp = B + (long long)n0 * ldb;

    wmma::fragment<wmma::accumulator, 16, 16, 16, float> acc[FM][2];
    #pragma unroll
    for (int i = 0; i < FM; i++)
        #pragma unroll
        for (int j = 0; j < 2; j++) wmma::fill_fragment(acc[i][j], 0.0f);

    float4 xa[NA4], xb[NB4];
    #pragma unroll
    for (int i = 0; i < NA4; i++) {
        int idx = t + 512 * i;
        xa[i] = *(const float4*)(Ap + (long long)(idx >> 3) * lda + (idx & 7) * 4);
    }
    #pragma unroll
    for (int i = 0; i < NB4; i++) {
        int idx = t + 512 * i;
        xb[i] = *(const float4*)(Bp + (long long)(idx >> 3) * ldb + (idx & 7) * 4);
    }
    {
        bf16 (*Ah)[40] = (bf16(*)[40])(sm);
        bf16 (*Al)[40] = (bf16(*)[40])(sm + TA);
        bf16 (*Bh)[40] = (bf16(*)[40])(sm + 2 * TA);
        bf16 (*Bl)[40] = (bf16(*)[40])(sm + 2 * TA + TB);
        #pragma unroll
        for (int i = 0; i < NA4; i++) {
            int idx = t + 512 * i;
            st_split(Ah, Al, idx, xa[i], bp, (idx & 7) * 4);
        }
        #pragma unroll
        for (int i = 0; i < NB4; i++) {
            int idx = t + 512 * i;
            st_split(Bh, Bl, idx, xb[i], (const float*)0, 0);
        }
    }
    __syncthreads();

    int stage = 0;
    for (int k0 = 0; k0 < K; k0 += 32) {
        bool nxt = (k0 + 32) < K;
        if (nxt) {
            int kn = k0 + 32;
            #pragma unroll
            for (int i = 0; i < NA4; i++) {
                int idx = t + 512 * i;
                xa[i] = *(const float4*)(Ap + (long long)(idx >> 3) * lda + kn + (idx & 7) * 4);
            }
            #pragma unroll
            for (int i = 0; i < NB4; i++) {
                int idx = t + 512 * i;
                xb[i] = *(const float4*)(Bp + (long long)(idx >> 3) * ldb + kn + (idx & 7) * 4);
            }
        }
        {
            bf16 (*Ah)[40] = (bf16(*)[40])(sm + stage * STAGE);
            bf16 (*Al)[40] = (bf16(*)[40])(sm + stage * STAGE + TA);
            bf16 (*Bh)[40] = (bf16(*)[40])(sm + stage * STAGE + 2 * TA);
            bf16 (*Bl)[40] = (bf16(*)[40])(sm + stage * STAGE + 2 * TA + TB);
            #pragma unroll
            for (int kk = 0; kk < 32; kk += 16) {
                wmma::fragment<wmma::matrix_a, 16, 16, 16, bf16, wmma::row_major> ah[FM], al[FM];
                wmma::fragment<wmma::matrix_b, 16, 16, 16, bf16, wmma::col_major> bh[2], bl[2];
                #pragma unroll
                for (int i = 0; i < FM; i++) {
                    wmma::load_matrix_sync(ah[i], &Ah[wm * 32 + i * 16][kk], 40);
                    wmma::load_matrix_sync(al[i], &Al[wm * 32 + i * 16][kk], 40);
                }
                #pragma unroll
                for (int j = 0; j < 2; j++) {
                    wmma::load_matrix_sync(bh[j], &Bh[wn * 32 + j * 16][kk], 40);
                    wmma::load_matrix_sync(bl[j], &Bl[wn * 32 + j * 16][kk], 40);
                }
                #pragma unroll
                for (int i = 0; i < FM; i++)
                    #pragma unroll
                    for (int j = 0; j < 2; j++) {
                        wmma::mma_sync(acc[i][j], ah[i], bh[j], acc[i][j]);
                        wmma::mma_sync(acc[i][j], ah[i], bl[j], acc[i][j]);
                        wmma::mma_sync(acc[i][j], al[i], bh[j], acc[i][j]);
                    }
            }
        }
        if (nxt) {
            int ns = stage ^ 1;
            bf16 (*Ah)[40] = (bf16(*)[40])(sm + ns * STAGE);
            bf16 (*Al)[40] = (bf16(*)[40])(sm + ns * STAGE + TA);
            bf16 (*Bh)[40] = (bf16(*)[40])(sm + ns * STAGE + 2 * TA);
            bf16 (*Bl)[40] = (bf16(*)[40])(sm + ns * STAGE + 2 * TA + TB);
            int kn = k0 + 32;
            #pragma unroll
            for (int i = 0; i < NA4; i++) {
                int idx = t + 512 * i;
                st_split(Ah, Al, idx, xa[i], bp, kn + (idx & 7) * 4);
            }
            #pragma unroll
            for (int i = 0; i < NB4; i++) {
                int idx = t + 512 * i;
                st_split(Bh, Bl, idx, xb[i], (const float*)0, 0);
            }
            __syncthreads();
            stage = ns;
        }
    }
    __syncthreads();

    // epilogue via per-warp SMEM scratch (aliases stage 0; synced above)
    float (*sc)[32][36] = (float(*)[32][36])sm;
    #pragma unroll
    for (int i = 0; i < FM; i++)
        #pragma unroll
        for (int j = 0; j < 2; j++)
            wmma::store_matrix_sync(&sc[w][i * 16][j * 16], acc[i][j], 36, wmma::mem_row_major);
    __syncwarp();

    int cn = n0 + wn * 32;
    int m = m0 + wm * 32 + lane;
    const float* srow = sc[w][lane];
    if (mode == 0) {
        float* cr = C + (long long)m * ldc + cn;
        #pragma unroll
        for (int j = 0; j < 32; j += 4)
            *(float4*)(cr + j) = make_float4(srow[j], srow[j + 1], srow[j + 2], srow[j + 3]);
    } else if (mode == 2) {
        float* cr = C + (long long)m * ldc + cn;
        #pragma unroll
        for (int j = 0; j < 32; j += 4) {
            float4 r;
            float x0 = srow[j], x1 = srow[j + 1], x2 = srow[j + 2], x3 = srow[j + 3];
            r.x = 0.5f * x0 * (1.0f + erff(x0 * 0.70710678f));
            r.y = 0.5f * x1 * (1.0f + erff(x1 * 0.70710678f));
            r.z = 0.5f * x2 * (1.0f + erff(x2 * 0.70710678f));
            r.w = 0.5f * x3 * (1.0f + erff(x3 * 0.70710678f));
            *(float4*)(cr + j) = r;
        }
    } else {   // mode 3: transposed store into [DM][SQ] (vt); coalesced per j
        #pragma unroll
        for (int j = 0; j < 32; j++)
            C[(long long)(cn + j) * SQ + m] = srow[j];
    }
}

template <int BM, int BN>
__global__ void __launch_bounds__(512) wgemm(
    const float* __restrict__ A, const float* __restrict__ B, float* __restrict__ C,
    int K, int lda, int ldb, int ldc, long long aZ, long long bZ, long long cZ,
    const float* __restrict__ bias, int mode)
{
    extern __shared__ char sm[];
    int z = blockIdx.z;
    wgemm_body<BM, BN>(sm,
        A + (long long)z * aZ, B + (long long)z * bZ, C + (long long)z * cZ,
        K, lda, ldb, ldc, bias ? bias + (long long)z * 64 : (const float*)0,
        blockIdx.y * BM, blockIdx.x * BN, mode);
}

// all 4 projections in one launch; z==2 (value) writes g_vt transposed
__global__ void __launch_bounds__(512) proj4(
    const float* __restrict__ query, const float* __restrict__ key,
    const float* __restrict__ value,
    const float* __restrict__ Wq, const float* __restrict__ Wke,
    const float* __restrict__ Wv, const float* __restrict__ Wkr)
{
    extern __shared__ char sm[];
    const float* A; const float* B; float* C; int mode = 0;
    switch (blockIdx.z) {
        case 0:  A = query; B = Wq;  C = g_q;    break;
        case 1:  A = key;   B = Wke; C = g_k;    break;
        case 2:  A = value; B = Wv;  C = g_vt; mode = 3; break;
        default: A = g_rel; B = Wkr; C = g_qrel; break;
    }
    wgemm_body<128, 128>(sm, A, B, C, DM, DM, DM, DM, (const float*)0,
                         blockIdx.y * 128, blockIdx.x * 128, mode);
}

// ---------------- fused score kernel (R11-validated) ----------------------
static constexpr int SF_QV_H = 0;
static constexpr int SF_QV_L = 18432;
static constexpr int SF_QR_H = 36864;
static constexpr int SF_QR_L = 73728;
static constexpr int SF_P    = 0;
static constexpr int SF_B    = 137216;
static constexpr int SF_SC   = 137216;
static constexpr int SF_E    = 210944;
static constexpr int SF_QL   = 211968;
static constexpr int SF_TOTAL = 212224;

__device__ __forceinline__ void split64(bf16 (*H)[72], bf16 (*L)[72],
    int r, int q, float4 x, const float* __restrict__ bias)
{
    float xv[4] = {x.x, x.y, x.z, x.w};
    if (bias) {
        #pragma unroll
        for (int e = 0; e < 4; e++) xv[e] += bias[q * 4 + e];
    }
    __align__(8) bf16 h[4], l[4];
    #pragma unroll
    for (int e = 0; e < 4; e++) {
        h[e] = __float2bfloat16(xv[e]);
        l[e] = __float2bfloat16(xv[e] - __bfloat162float(h[e]));
    }
    *(uint2*)&H[r][q * 4] = *(uint2*)h;
    *(uint2*)&L[r][q * 4] = *(uint2*)l;
}

__global__ void __launch_bounds__(512) score_fused(
    const float* __restrict__ u_p, const float* __restrict__ v_p,
    float* __restrict__ Wout)
{
    extern __shared__ char sm[];
    int t = threadIdx.x, w = t >> 5;
    int f0 = blockIdx.x * 128, s0 = blockIdx.y * 128, h = blockIdx.z;
    int g0 = f0 - s0;
    int n1 = min(g0 + 127, 0) - g0 + 128; if (n1 < 0) n1 = 0;
    int gBmin = max(g0 - 127, 2);
    int n2 = g0 + 127 - gBmin + 1; if (n2 < 0) n2 = 0;
    const float* uq = u_p + h * 64;
    const float* vq = v_p + h * 64;
    bool needE = (g0 >= 128);

    bf16 (*qvH)[72] = (bf16(*)[72])(sm + SF_QV_H);
    bf16 (*qvL)[72] = (bf16(*)[72])(sm + SF_QV_L);
    bf16 (*qrH)[72] = (bf16(*)[72])(sm + SF_QR_H);
    bf16 (*qrL)[72] = (bf16(*)[72])(sm + SF_QR_L);
    bf16 (*quH)[72] = (bf16(*)[72])(sm + SF_B);
    bf16 (*quL)[72] = (bf16(*)[72])(sm + SF_B + 18432);
    bf16 (*kH)[72]  = (bf16(*)[72])(sm + SF_B + 36864);
    bf16 (*kL)[72]  = (bf16(*)[72])(sm + SF_B + 55296);
    float* Ebuf = (float*)(sm + SF_E);
    float* qlS  = (float*)(sm + SF_QL);

    #pragma unroll
    for (int i = 0; i < 4; i++) {
        int idx = t + 512 * i;
        int r = idx >> 4, q = idx & 15;
        float4 x = *(const float4*)(g_q + (long long)(s0 + r) * DM + h * 64 + q * 4);
        split64(qvH, qvL, r, q, x, vq);
    }
    #pragma unroll
    for (int i = 0; i < 8; i++) {
        int idx = t + 512 * i;
        int r = idx >> 4, q = idx & 15;
        int wr = (r < n1) ? (1920 + g0 + r) : ((r - n1 < n2) ? (gBmin - 2 + (r - n1)) : 0);
        float4 x = *(const float4*)(g_qrel + (long long)wr * DM + h * 64 + q * 4);
        split64(qrH, qrL, r, q, x, (const float*)0);
    }
    #pragma unroll
    for (int i = 0; i < 4; i++) {
        int idx = t + 512 * i;
        int r = idx >> 4, q = idx & 15;
        float4 x = *(const float4*)(g_q + (long long)(s0 + r) * DM + h * 64 + q * 4);
        split64(quH, quL, r, q, x, uq);
    }
    #pragma unroll
    for (int i = 0; i < 4; i++) {
        int idx = t + 512 * i;
        int r = idx >> 4, q = idx & 15;
        float4 x = *(const float4*)(g_k + (long long)(f0 + r) * DM + h * 64 + q * 4);
        split64(kH, kL, r, q, x, (const float*)0);
    }
    if (needE && t < 64)
        qlS[t] = g_q[(long long)(s0 + 128) * DM + h * 64 + t] + vq[t];
    __syncthreads();

    int wm = w >> 2, wn = w & 3;
    {
        wmma::fragment<wmma::accumulator, 16, 16, 16, float> accP[2][4];
        #pragma unroll
        for (int i = 0; i < 2; i++)
            #pragma unroll
            for (int n = 0; n < 4; n++) wmma::fill_fragment(accP[i][n], 0.0f);
        #pragma unroll
        for (int k4 = 0; k4 < 4; k4++) {
            #pragma unroll
            for (int n = 0; n < 4; n++) {
                wmma::fragment<wmma::matrix_b, 16, 16, 16, bf16, wmma::col_major> bh, bl;
                wmma::load_matrix_sync(bh, &qrH[wn * 64 + n * 16][k4 * 16], 72);
                wmma::load_matrix_sync(bl, &qrL[wn * 64 + n * 16][k4 * 16], 72);
                #pragma unroll
                for (int i = 0; i < 2; i++) {
                    wmma::fragment<wmma::matrix_a, 16, 16, 16, bf16, wmma::row_major> ah, al;
                    wmma::load_matrix_sync(ah, &qvH[wm * 32 + i * 16][k4 * 16], 72);
                    wmma::load_matrix_sync(al, &qvL[wm * 32 + i * 16][k4 * 16], 72);
                    wmma::mma_sync(accP[i][n], ah, bh, accP[i][n]);
                    wmma::mma_sync(accP[i][n], ah, bl, accP[i][n]);
                    wmma::mma_sync(accP[i][n], al, bh, accP[i][n]);
                }
            }
        }
        if (needE && t < 256 && t < n1 + n2) {
            float a = 0.0f;
            #pragma unroll 8
            for (int k = 0; k < 64; k++)
                a += qlS[k] * (__bfloat162float(qrH[t][k]) + __bfloat162float(qrL[t][k]));
            Ebuf[t] = a;
        }
        __syncthreads();
        float (*P)[268] = (float(*)[268])(sm + SF_P);
        #pragma unroll
        for (int i = 0; i < 2; i++)
            #pragma unroll
            for (int n = 0; n < 4; n++)
                wmma::store_matrix_sync(&P[wm * 32 + i * 16][wn * 64 + n * 16],
                                        accP[i][n], 268, wmma::mem_row_major);
    }

    wmma::fragment<wmma::accumulator, 16, 16, 16, float> acc2[2][2];
    #pragma unroll
    for (int i = 0; i < 2; i++)
        #pragma unroll
        for (int n = 0; n < 2; n++) wmma::fill_fragment(acc2[i][n], 0.0f);
    #pragma unroll
    for (int k4 = 0; k4 < 4; k4++) {
        #pragma unroll
        for (int n = 0; n < 2; n++) {
            wmma::fragment<wmma::matrix_b, 16, 16, 16, bf16, wmma::col_major> bh, bl;
            wmma::load_matrix_sync(bh, &kH[wn * 32 + n * 16][k4 * 16], 72);
            wmma::load_matrix_sync(bl, &kL[wn * 32 + n * 16][k4 * 16], 72);
            #pragma unroll
            for (int i = 0; i < 2; i++) {
                wmma::fragment<wmma::matrix_a, 16, 16, 16, bf16, wmma::row_major> ah, al;
                wmma::load_matrix_sync(ah, &quH[wm * 32 + i * 16][k4 * 16], 72);
                wmma::load_matrix_sync(al, &quL[wm * 32 + i * 16][k4 * 16], 72);
                wmma::mma_sync(acc2[i][n], ah, bh, acc2[i][n]);
                wmma::mma_sync(acc2[i][n], ah, bl, acc2[i][n]);
                wmma::mma_sync(acc2[i][n], al, bh, acc2[i][n]);
            }
        }
    }
    __syncthreads();
    float (*scr)[32][36] = (float(*)[32][36])(sm + SF_SC);
    #pragma unroll
    for (int i = 0; i < 2; i++)
        #pragma unroll
        for (int n = 0; n < 2; n++)
            wmma::store_matrix_sync(&scr[w][i * 16][n * 16], acc2[i][n], 36,
                                    wmma::mem_row_major);
    __syncthreads();

    {
        float (*P)[268] = (float(*)[268])(sm + SF_P);
        int row = t >> 2, cs = (t & 3) * 32;
        int s = s0 + row;
        const float* srow = scr[(row >> 5) * 4 + (t & 3)][row & 31];
        float* co = Wout + (long long)h * SS + (long long)s * SQ + f0 + cs;
        #pragma unroll
        for (int j0 = 0; j0 < 32; j0 += 4) {
            float o[4];
            #pragma unroll
            for (int e = 0; e < 4; e++) {
                int j = j0 + e;
                int f = f0 + cs + j;
                int g = f - s;
                float bd;
                if (g <= 0)       bd = P[row][g - g0 + 127];
                else if (g == 1)  bd = 0.0f;
                else {
                    int jj = n1 + g - gBmin;
                    bd = (row < 127) ? P[row + 1][jj] : Ebuf[jj];
                }
                o[e] = (srow[j] + bd) * 0.03125f;
            }
            *(float4*)(co + j0) = make_float4(o[0], o[1], o[2], o[3]);
        }
    }
}

// ---------------- softmax + loss ----------------
__global__ void __launch_bounds__(256) softmax_kernel(float* __restrict__ W) {
    int s = blockIdx.x, h = blockIdx.y;
    float* row = W + ((long long)h * SQ + s) * SQ;
    int t = threadIdx.x;
    float4 v0 = *(float4*)(row + t * 8);
    float4 v1 = *(float4*)(row + t * 8 + 4);
    float vm = fmaxf(fmaxf(fmaxf(v0.x, v0.y), fmaxf(v0.z, v0.w)),
                     fmaxf(fmaxf(v1.x, v1.y), fmaxf(v1.z, v1.w)));
    __shared__ float red[8];
    int lane = t & 31, wid = t >> 5;
    #pragma unroll
    for (int o = 16; o > 0; o >>= 1) vm = fmaxf(vm, __shfl_xor_sync(0xffffffffu, vm, o));
    if (lane == 0) red[wid] = vm;
    __syncthreads();
    float M = red[0];
    #pragma unroll
    for (int i = 1; i < 8; i++) M = fmaxf(M, red[i]);
    __syncthreads();
    float e[8];
    e[0] = __expf(v0.x - M); e[1] = __expf(v0.y - M);
    e[2] = __expf(v0.z - M); e[3] = __expf(v0.w - M);
    e[4] = __expf(v1.x - M); e[5] = __expf(v1.y - M);
    e[6] = __expf(v1.z - M); e[7] = __expf(v1.w - M);
    float sum = ((e[0] + e[1]) + (e[2] + e[3])) + ((e[4] + e[5]) + (e[6] + e[7]));
    #pragma unroll
    for (int o = 16; o > 0; o >>= 1) sum += __shfl_xor_sync(0xffffffffu, sum, o);
    if (lane == 0) red[wid] = sum;
    __syncthreads();
    float T = red[0];
    #pragma unroll
    for (int i = 1; i < 8; i++) T += red[i];
    float inv = 1.0f / T;
    *(float4*)(row + t * 8)     = make_float4(e[0] * inv, e[1] * inv, e[2] * inv, e[3] * inv);
    *(float4*)(row + t * 8 + 4) = make_float4(e[4] * inv, e[5] * inv, e[6] * inv, e[7] * inv);
    if (t == 0) atomicMax(&g_headmax[h], __float_as_uint(inv));
}

__global__ void loss_kernel(float* __restrict__ loss) {
    if (threadIdx.x == 0) {
        float s = 0.0f;
        #pragma unroll
        for (int h = 0; h < NH; h++) s += __uint_as_float(g_headmax[h]);
        loss[0] = s / (float)NH;
    }
}

// ---------------- launch ----------------
extern "C" void kernel_launch(void* const* d_in, const int* in_sizes, int n_in,
                              void* d_out, int out_size)
{
    const float* query = (const float*)d_in[0];
    const float* key   = (const float*)d_in[1];
    const float* value = (const float*)d_in[2];
    const float* Wq    = (const float*)d_in[4];
    const float* Wke   = (const float*)d_in[5];
    const float* Wkr   = (const float*)d_in[6];
    const float* Wv    = (const float*)d_in[7];
    const float* Wf    = (const float*)d_in[8];
    const float* u_p   = (const float*)d_in[9];
    const float* v_p   = (const float*)d_in[10];

    float* out  = (float*)d_out;
    float* Wt   = out + (long long)SQ * DM;
    float* loss = Wt + (long long)NH * SS;

    float *fvt, *fctx;
    cudaGetSymbolAddress((void**)&fvt,  g_vt);
    cudaGetSymbolAddress((void**)&fctx, g_ctx);

    // DSM: max(2 stages, 16x32x36 f32 scratch = 73728)
    const int DSM_128_128 = 2 * (2 * 128 * 80 + 2 * 128 * 80);   // 81920
    const int DSM_256_64  = 2 * (2 * 256 * 80 + 2 * 64 * 80);    // 102400
    cudaFuncSetAttribute(proj4, cudaFuncAttributeMaxDynamicSharedMemorySize, DSM_128_128);
    cudaFuncSetAttribute(wgemm<128, 128>, cudaFuncAttributeMaxDynamicSharedMemorySize, DSM_128_128);
    cudaFuncSetAttribute(wgemm<256, 64>,  cudaFuncAttributeMaxDynamicSharedMemorySize, DSM_256_64);
    cudaFuncSetAttribute(score_fused, cudaFuncAttributeMaxDynamicSharedMemorySize, SF_TOTAL);

    relenc_kernel<<<(SQ * DM) / 256, 256>>>();

    // 4 projections, one launch; value-projection writes vt directly
    proj4<<<dim3(DM / 128, SQ / 128, 4), 512, DSM_128_128>>>(
        query, key, value, Wq, Wke, Wv, Wkr);

    // fused score: A_C + rel-shifted B_D computed in-tile
    score_fused<<<dim3(SQ / 128, SQ / 128, NH), 512, SF_TOTAL>>>(u_p, v_p, Wt);

    softmax_kernel<<<dim3(SQ, NH), 256>>>(Wt);
    loss_kernel<<<1, 32>>>(loss);

    // ctx[:, h*64:(h+1)*64] = W[h] @ v_h  (BM=256 tiles, one wave of 128 blocks)
    wgemm<256, 64><<<dim3(1, SQ / 256, NH), 512, DSM_256_64>>>(
        Wt, fvt, fctx, SQ, SQ, SQ, DM, SS, (long long)64 * SQ, 64, 0, 0);

    wgemm<128, 128><<<dim3(DM / 128, SQ / 128, 1), 512, DSM_128_128>>>(
        fctx, Wf, out, DM, DM, DM, DM, 0, 0, 0, 0, 2);
}

// round 13
// speedup vs baseline: 1.0458x; 1.0458x over previous
#include <cuda_runtime.h>
#include <cuda_bf16.h>
#include <mma.h>
#include <math.h>
#include <stdint.h>

using namespace nvcuda;
typedef __nv_bfloat16 bf16;
static constexpr int SQ = 2048, DM = 1024, NH = 16;
static constexpr long long SS = (long long)SQ * SQ;

__device__ float g_rel[SQ*DM], g_q[SQ*DM], g_k[SQ*DM];
__device__ float g_qrel[SQ*DM], g_vt[DM*SQ], g_ctx[SQ*DM];
__device__ float g_psum[NH*SQ*16], g_pmax[NH*SQ*16];
__device__ float g_rowinv[NH*SQ], g_rowwmax[NH*SQ];

// ---------------- small kernels ----------------
__global__ void relenc_kernel() {
    int idx = blockIdx.x * blockDim.x + threadIdx.x;
    if (idx >= SQ * DM) return;
    int f = idx >> 10, c = idx & (DM - 1);
    int p = SQ - 1 - f, i2 = c & ~1;
    double dv = exp(-((double)i2 / (double)DM) * log(10000.0));
    float angf = (float)p * (float)dv;
    double a = (double)angf;
    g_rel[idx] = (float)((c & 1) ? cos(a) : sin(a));
}

// split one float4 into hi/lo bf16 quads; store at pitch-40 layout
__device__ __forceinline__ void st_split(bf16 (*H)[40], bf16 (*L)[40],
    int idx, float4 x, const float* __restrict__ bias, int kcol)
{
    float xv[4] = {x.x, x.y, x.z, x.w};
    if (bias) {
        #pragma unroll
        for (int e = 0; e < 4; e++) xv[e] += bias[kcol + e];
    }
    __align__(8) bf16 h[4], l[4];
    #pragma unroll
    for (int e = 0; e < 4; e++) {
        h[e] = __float2bfloat16(xv[e]);
        l[e] = __float2bfloat16(xv[e] - __bfloat162float(h[e]));
    }
    int r = idx >> 3, c = (idx & 7) * 4;
    *(uint2*)&H[r][c] = *(uint2*)h;
    *(uint2*)&L[r][c] = *(uint2*)l;
}

// ---------------- split-bf16 WMMA GEMM body: 512 threads, 16 warps --------
template <int BM, int BN>
__device__ __forceinline__ void wgemm_body(char* sm,
    const float* __restrict__ A, const float* __restrict__ B, float* __restrict__ C,
    int K, int lda, int ldb, int ldc, const float* __restrict__ bp,
    int m0, int n0, int mode)
{
    constexpr int NWN = BN / 32;
    constexpr int NWM = 16 / NWN;
    constexpr int FM  = BM / (NWM * 16);
    constexpr int TA  = BM * 40 * 2;
    constexpr int TB  = BN * 40 * 2;
    constexpr int STAGE = 2 * TA + 2 * TB;
    constexpr int NA4 = BM / 64;
    constexpr int NB4 = BN / 64 > 0 ? BN / 64 : 1;

    int t = threadIdx.x, w = t >> 5, lane = t & 31;
    int wm = w / NWN, wn = w % NWN;
    const float* Ap = A + (long long)m0 * lda;
    const float* Bp = B + (long long)n0 * ldb;

    wmma::fragment<wmma::accumulator, 16, 16, 16, float> acc[FM][2];
    #pragma unroll
    for (int i = 0; i < FM; i++)
        #pragma unroll
        for (int j = 0; j < 2; j++) wmma::fill_fragment(acc[i][j], 0.0f);

    float4 xa[NA4], xb[NB4];
    #pragma unroll
    for (int i = 0; i < NA4; i++) {
        int idx = t + 512 * i;
        xa[i] = *(const float4*)(Ap + (long long)(idx >> 3) * lda + (idx & 7) * 4);
    }
    #pragma unroll
    for (int i = 0; i < NB4; i++) {
        int idx = t + 512 * i;
        xb[i] = *(const float4*)(Bp + (long long)(idx >> 3) * ldb + (idx & 7) * 4);
    }
    {
        bf16 (*Ah)[40] = (bf16(*)[40])(sm);
        bf16 (*Al)[40] = (bf16(*)[40])(sm + TA);
        bf16 (*Bh)[40] = (bf16(*)[40])(sm + 2 * TA);
        bf16 (*Bl)[40] = (bf16(*)[40])(sm + 2 * TA + TB);
        #pragma unroll
        for (int i = 0; i < NA4; i++) {
            int idx = t + 512 * i;
            st_split(Ah, Al, idx, xa[i], bp, (idx & 7) * 4);
        }
        #pragma unroll
        for (int i = 0; i < NB4; i++) {
            int idx = t + 512 * i;
            st_split(Bh, Bl, idx, xb[i], (const float*)0, 0);
        }
    }
    __syncthreads();

    int stage = 0;
    for (int k0 = 0; k0 < K; k0 += 32) {
        bool nxt = (k0 + 32) < K;
        if (nxt) {
            int kn = k0 + 32;
            #pragma unroll
            for (int i = 0; i < NA4; i++) {
                int idx = t + 512 * i;
                xa[i] = *(const float4*)(Ap + (long long)(idx >> 3) * lda + kn + (idx & 7) * 4);
            }
            #pragma unroll
            for (int i = 0; i < NB4; i++) {
                int idx = t + 512 * i;
                xb[i] = *(const float4*)(Bp + (long long)(idx >> 3) * ldb + kn + (idx & 7) * 4);
            }
        }
        {
            bf16 (*Ah)[40] = (bf16(*)[40])(sm + stage * STAGE);
            bf16 (*Al)[40] = (bf16(*)[40])(sm + stage * STAGE + TA);
            bf16 (*Bh)[40] = (bf16(*)[40])(sm + stage * STAGE + 2 * TA);
            bf16 (*Bl)[40] = (bf16(*)[40])(sm + stage * STAGE + 2 * TA + TB);
            #pragma unroll
            for (int kk = 0; kk < 32; kk += 16) {
                wmma::fragment<wmma::matrix_a, 16, 16, 16, bf16, wmma::row_major> ah[FM], al[FM];
                wmma::fragment<wmma::matrix_b, 16, 16, 16, bf16, wmma::col_major> bh[2], bl[2];
                #pragma unroll
                for (int i = 0; i < FM; i++) {
                    wmma::load_matrix_sync(ah[i], &Ah[wm * 32 + i * 16][kk], 40);
                    wmma::load_matrix_sync(al[i], &Al[wm * 32 + i * 16][kk], 40);
                }
                #pragma unroll
                for (int j = 0; j < 2; j++) {
                    wmma::load_matrix_sync(bh[j], &Bh[wn * 32 + j * 16][kk], 40);
                    wmma::load_matrix_sync(bl[j], &Bl[wn * 32 + j * 16][kk], 40);
                }
                #pragma unroll
                for (int i = 0; i < FM; i++)
                    #pragma unroll
                    for (int j = 0; j < 2; j++) {
                        wmma::mma_sync(acc[i][j], ah[i], bh[j], acc[i][j]);
                        wmma::mma_sync(acc[i][j], ah[i], bl[j], acc[i][j]);
                        wmma::mma_sync(acc[i][j], al[i], bh[j], acc[i][j]);
                    }
            }
        }
        if (nxt) {
            int ns = stage ^ 1;
            bf16 (*Ah)[40] = (bf16(*)[40])(sm + ns * STAGE);
            bf16 (*Al)[40] = (bf16(*)[40])(sm + ns * STAGE + TA);
            bf16 (*Bh)[40] = (bf16(*)[40])(sm + ns * STAGE + 2 * TA);
            bf16 (*Bl)[40] = (bf16(*)[40])(sm + ns * STAGE + 2 * TA + TB);
            int kn = k0 + 32;
            #pragma unroll
            for (int i = 0; i < NA4; i++) {
                int idx = t + 512 * i;
                st_split(Ah, Al, idx, xa[i], bp, kn + (idx & 7) * 4);
            }
            #pragma unroll
            for (int i = 0; i < NB4; i++) {
                int idx = t + 512 * i;
                st_split(Bh, Bl, idx, xb[i], (const float*)0, 0);
            }
            __syncthreads();
            stage = ns;
        }
    }
    __syncthreads();

    float (*sc)[32][36] = (float(*)[32][36])sm;
    #pragma unroll
    for (int i = 0; i < FM; i++)
        #pragma unroll
        for (int j = 0; j < 2; j++)
            wmma::store_matrix_sync(&sc[w][i * 16][j * 16], acc[i][j], 36, wmma::mem_row_major);
    __syncwarp();

    int cn = n0 + wn * 32;
    int m = m0 + wm * 32 + lane;
    const float* srow = sc[w][lane];
    if (mode == 0) {
        float* cr = C + (long long)m * ldc + cn;
        #pragma unroll
        for (int j = 0; j < 32; j += 4)
            *(float4*)(cr + j) = make_float4(srow[j], srow[j + 1], srow[j + 2], srow[j + 3]);
    } else if (mode == 2) {
        float* cr = C + (long long)m * ldc + cn;
        #pragma unroll
        for (int j = 0; j < 32; j += 4) {
            float4 r;
            float x0 = srow[j], x1 = srow[j + 1], x2 = srow[j + 2], x3 = srow[j + 3];
            r.x = 0.5f * x0 * (1.0f + erff(x0 * 0.70710678f));
            r.y = 0.5f * x1 * (1.0f + erff(x1 * 0.70710678f));
            r.z = 0.5f * x2 * (1.0f + erff(x2 * 0.70710678f));
            r.w = 0.5f * x3 * (1.0f + erff(x3 * 0.70710678f));
            *(float4*)(cr + j) = r;
        }
    } else {   // mode 3: transposed store into [DM][SQ] (vt)
        #pragma unroll
        for (int j = 0; j < 32; j++)
            C[(long long)(cn + j) * SQ + m] = srow[j];
    }
}

template <int BM, int BN>
__global__ void __launch_bounds__(512) wgemm(
    const float* __restrict__ A, const float* __restrict__ B, float* __restrict__ C,
    int K, int lda, int ldb, int ldc, long long aZ, long long bZ, long long cZ,
    const float* __restrict__ bias, int mode)
{
    extern __shared__ char sm[];
    int z = blockIdx.z;
    wgemm_body<BM, BN>(sm,
        A + (long long)z * aZ, B + (long long)z * bZ, C + (long long)z * cZ,
        K, lda, ldb, ldc, bias ? bias + (long long)z * 64 : (const float*)0,
        blockIdx.y * BM, blockIdx.x * BN, mode);
}

// all 4 projections in one launch; z==2 (value) writes g_vt transposed
__global__ void __launch_bounds__(512) proj4(
    const float* __restrict__ query, const float* __restrict__ key,
    const float* __restrict__ value,
    const float* __restrict__ Wq, const float* __restrict__ Wke,
    const float* __restrict__ Wv, const float* __restrict__ Wkr)
{
    extern __shared__ char sm[];
    const float* A; const float* B; float* C; int mode = 0;
    switch (blockIdx.z) {
        case 0:  A = query; B = Wq;  C = g_q;    break;
        case 1:  A = key;   B = Wke; C = g_k;    break;
        case 2:  A = value; B = Wv;  C = g_vt; mode = 3; break;
        default: A = g_rel; B = Wkr; C = g_qrel; break;
    }
    wgemm_body<128, 128>(sm, A, B, C, DM, DM, DM, DM, (const float*)0,
                         blockIdx.y * 128, blockIdx.x * 128, mode);
}

// ---------------- fused score kernel (+ exp + row partials) ---------------
static constexpr int SF_QV_H = 0;
static constexpr int SF_QV_L = 18432;
static constexpr int SF_QR_H = 36864;
static constexpr int SF_QR_L = 73728;
static constexpr int SF_P    = 0;
static constexpr int SF_B    = 137216;
static constexpr int SF_SC   = 137216;
static constexpr int SF_E    = 210944;
static constexpr int SF_QL   = 211968;
static constexpr int SF_TOTAL = 212224;

__device__ __forceinline__ void split64(bf16 (*H)[72], bf16 (*L)[72],
    int r, int q, float4 x, const float* __restrict__ bias)
{
    float xv[4] = {x.x, x.y, x.z, x.w};
    if (bias) {
        #pragma unroll
        for (int e = 0; e < 4; e++) xv[e] += bias[q * 4 + e];
    }
    __align__(8) bf16 h[4], l[4];
    #pragma unroll
    for (int e = 0; e < 4; e++) {
        h[e] = __float2bfloat16(xv[e]);
        l[e] = __float2bfloat16(xv[e] - __bfloat162float(h[e]));
    }
    *(uint2*)&H[r][q * 4] = *(uint2*)h;
    *(uint2*)&L[r][q * 4] = *(uint2*)l;
}

__global__ void __launch_bounds__(512) score_fused(
    const float* __restrict__ u_p, const float* __restrict__ v_p,
    float* __restrict__ Wout)
{
    extern __shared__ char sm[];
    int t = threadIdx.x, w = t >> 5;
    int f0 = blockIdx.x * 128, s0 = blockIdx.y * 128, h = blockIdx.z;
    int g0 = f0 - s0;
    int n1 = min(g0 + 127, 0) - g0 + 128; if (n1 < 0) n1 = 0;
    int gBmin = max(g0 - 127, 2);
    int n2 = g0 + 127 - gBmin + 1; if (n2 < 0) n2 = 0;
    const float* uq = u_p + h * 64;
    const float* vq = v_p + h * 64;
    bool needE = (g0 >= 128);

    bf16 (*qvH)[72] = (bf16(*)[72])(sm + SF_QV_H);
    bf16 (*qvL)[72] = (bf16(*)[72])(sm + SF_QV_L);
    bf16 (*qrH)[72] = (bf16(*)[72])(sm + SF_QR_H);
    bf16 (*qrL)[72] = (bf16(*)[72])(sm + SF_QR_L);
    bf16 (*quH)[72] = (bf16(*)[72])(sm + SF_B);
    bf16 (*quL)[72] = (bf16(*)[72])(sm + SF_B + 18432);
    bf16 (*kH)[72]  = (bf16(*)[72])(sm + SF_B + 36864);
    bf16 (*kL)[72]  = (bf16(*)[72])(sm + SF_B + 55296);
    float* Ebuf = (float*)(sm + SF_E);
    float* qlS  = (float*)(sm + SF_QL);

    #pragma unroll
    for (int i = 0; i < 4; i++) {
        int idx = t + 512 * i;
        int r = idx >> 4, q = idx & 15;
        float4 x = *(const float4*)(g_q + (long long)(s0 + r) * DM + h * 64 + q * 4);
        split64(qvH, qvL, r, q, x, vq);
    }
    #pragma unroll
    for (int i = 0; i < 8; i++) {
        int idx = t + 512 * i;
        int r = idx >> 4, q = idx & 15;
        int wr = (r < n1) ? (1920 + g0 + r) : ((r - n1 < n2) ? (gBmin - 2 + (r - n1)) : 0);
        float4 x = *(const float4*)(g_qrel + (long long)wr * DM + h * 64 + q * 4);
        split64(qrH, qrL, r, q, x, (const float*)0);
    }
    #pragma unroll
    for (int i = 0; i < 4; i++) {
        int idx = t + 512 * i;
        int r = idx >> 4, q = idx & 15;
        float4 x = *(const float4*)(g_q + (long long)(s0 + r) * DM + h * 64 + q * 4);
        split64(quH, quL, r, q, x, uq);
    }
    #pragma unroll
    for (int i = 0; i < 4; i++) {
        int idx = t + 512 * i;
        int r = idx >> 4, q = idx & 15;
        float4 x = *(const float4*)(g_k + (long long)(f0 + r) * DM + h * 64 + q * 4);
        split64(kH, kL, r, q, x, (const float*)0);
    }
    if (needE && t < 64)
        qlS[t] = g_q[(long long)(s0 + 128) * DM + h * 64 + t] + vq[t];
    __syncthreads();

    int wm = w >> 2, wn = w & 3;
    {
        wmma::fragment<wmma::accumulator, 16, 16, 16, float> accP[2][4];
        #pragma unroll
        for (int i = 0; i < 2; i++)
            #pragma unroll
            for (int n = 0; n < 4; n++) wmma::fill_fragment(accP[i][n], 0.0f);
        #pragma unroll
        for (int k4 = 0; k4 < 4; k4++) {
            #pragma unroll
            for (int n = 0; n < 4; n++) {
                wmma::fragment<wmma::matrix_b, 16, 16, 16, bf16, wmma::col_major> bh, bl;
                wmma::load_matrix_sync(bh, &qrH[wn * 64 + n * 16][k4 * 16], 72);
                wmma::load_matrix_sync(bl, &qrL[wn * 64 + n * 16][k4 * 16], 72);
                #pragma unroll
                for (int i = 0; i < 2; i++) {
                    wmma::fragment<wmma::matrix_a, 16, 16, 16, bf16, wmma::row_major> ah, al;
                    wmma::load_matrix_sync(ah, &qvH[wm * 32 + i * 16][k4 * 16], 72);
                    wmma::load_matrix_sync(al, &qvL[wm * 32 + i * 16][k4 * 16], 72);
                    wmma::mma_sync(accP[i][n], ah, bh, accP[i][n]);
                    wmma::mma_sync(accP[i][n], ah, bl, accP[i][n]);
                    wmma::mma_sync(accP[i][n], al, bh, accP[i][n]);
                }
            }
        }
        if (needE && t < 256 && t < n1 + n2) {
            float a = 0.0f;
            #pragma unroll 8
            for (int k = 0; k < 64; k++)
                a += qlS[k] * (__bfloat162float(qrH[t][k]) + __bfloat162float(qrL[t][k]));
            Ebuf[t] = a;
        }
        __syncthreads();
        float (*P)[268] = (float(*)[268])(sm + SF_P);
        #pragma unroll
        for (int i = 0; i < 2; i++)
            #pragma unroll
            for (int n = 0; n < 4; n++)
                wmma::store_matrix_sync(&P[wm * 32 + i * 16][wn * 64 + n * 16],
                                        accP[i][n], 268, wmma::mem_row_major);
    }

    wmma::fragment<wmma::accumulator, 16, 16, 16, float> acc2[2][2];
    #pragma unroll
    for (int i = 0; i < 2; i++)
        #pragma unroll
        for (int n = 0; n < 2; n++) wmma::fill_fragment(acc2[i][n], 0.0f);
    #pragma unroll
    for (int k4 = 0; k4 < 4; k4++) {
        #pragma unroll
        for (int n = 0; n < 2; n++) {
            wmma::fragment<wmma::matrix_b, 16, 16, 16, bf16, wmma::col_major> bh, bl;
            wmma::load_matrix_sync(bh, &kH[wn * 32 + n * 16][k4 * 16], 72);
            wmma::load_matrix_sync(bl, &kL[wn * 32 + n * 16][k4 * 16], 72);
            #pragma unroll
            for (int i = 0; i < 2; i++) {
                wmma::fragment<wmma::matrix_a, 16, 16, 16, bf16, wmma::row_major> ah, al;
                wmma::load_matrix_sync(ah, &quH[wm * 32 + i * 16][k4 * 16], 72);
                wmma::load_matrix_sync(al, &quL[wm * 32 + i * 16][k4 * 16], 72);
                wmma::mma_sync(acc2[i][n], ah, bh, acc2[i][n]);
                wmma::mma_sync(acc2[i][n], ah, bl, acc2[i][n]);
                wmma::mma_sync(acc2[i][n], al, bh, acc2[i][n]);
            }
        }
    }
    __syncthreads();
    float (*scr)[32][36] = (float(*)[32][36])(sm + SF_SC);
    #pragma unroll
    for (int i = 0; i < 2; i++)
        #pragma unroll
        for (int n = 0; n < 2; n++)
            wmma::store_matrix_sync(&scr[w][i * 16][n * 16], acc2[i][n], 36,
                                    wmma::mem_row_major);
    __syncthreads();

    // epilogue: BD gather, scale, e = exp, store + row partial sum/max
    {
        float (*P)[268] = (float(*)[268])(sm + SF_P);
        int row = t >> 2, cs = (t & 3) * 32;
        int s = s0 + row;
        const float* srow = scr[(row >> 5) * 4 + (t & 3)][row & 31];
        float* co = Wout + (long long)h * SS + (long long)s * SQ + f0 + cs;
        float tsum = 0.0f, tmax = 0.0f;
        #pragma unroll
        for (int j0 = 0; j0 < 32; j0 += 4) {
            float o[4];
            #pragma unroll
            for (int e = 0; e < 4; e++) {
                int j = j0 + e;
                int f = f0 + cs + j;
                int g = f - s;
                float bd;
                if (g <= 0)       bd = P[row][g - g0 + 127];
                else if (g == 1)  bd = 0.0f;
                else {
                    int jj = n1 + g - gBmin;
                    bd = (row < 127) ? P[row + 1][jj] : Ebuf[jj];
                }
                float sc_ = (srow[j] + bd) * 0.03125f;
                float ev = __expf(sc_);
                o[e] = ev;
                tsum += ev;
                tmax = fmaxf(tmax, ev);
            }
            *(float4*)(co + j0) = make_float4(o[0], o[1], o[2], o[3]);
        }
        // reduce across the 4 threads owning this row (aligned lane groups)
        tsum += __shfl_xor_sync(0xffffffffu, tsum, 1);
        tsum += __shfl_xor_sync(0xffffffffu, tsum, 2);
        tmax = fmaxf(tmax, __shfl_xor_sync(0xffffffffu, tmax, 1));
        tmax = fmaxf(tmax, __shfl_xor_sync(0xffffffffu, tmax, 2));
        if ((t & 3) == 0) {
            int ridx = (((h * SQ) + s) << 4) + blockIdx.x;
            g_psum[ridx] = tsum;
            g_pmax[ridx] = tmax;
        }
    }
}

// ---------------- row stats + loss ----------------
__global__ void stat_kernel() {
    int idx = blockIdx.x * 256 + threadIdx.x;
    if (idx >= NH * SQ) return;
    const float* ps = g_psum + ((long long)idx << 4);
    const float* pm = g_pmax + ((long long)idx << 4);
    float s = 0.0f, m = 0.0f;
    #pragma unroll
    for (int i = 0; i < 16; i++) { s += ps[i]; m = fmaxf(m, pm[i]); }
    float inv = 1.0f / s;
    g_rowinv[idx]  = inv;
    g_rowwmax[idx] = m * inv;
}

__global__ void __launch_bounds__(256) loss_kernel(float* __restrict__ loss) {
    __shared__ float red[8];
    int t = threadIdx.x, lane = t & 31, wid = t >> 5;
    float total = 0.0f;
    for (int h = 0; h < NH; h++) {
        float m = 0.0f;
        for (int r = t; r < SQ; r += 256) m = fmaxf(m, g_rowwmax[h * SQ + r]);
        #pragma unroll
        for (int o = 16; o > 0; o >>= 1) m = fmaxf(m, __shfl_xor_sync(0xffffffffu, m, o));
        if (lane == 0) red[wid] = m;
        __syncthreads();
        if (t == 0) {
            float M = red[0];
            #pragma unroll
            for (int i = 1; i < 8; i++) M = fmaxf(M, red[i]);
            total += M;
        }
        __syncthreads();
    }
    if (t == 0) loss[0] = total / (float)NH;
}

// ---------------- av with fused normalization + W writeback ---------------
// BM=256, BN=64, 512 thr, 16 warps (8x2). A = e (raw exp) from Wt; loader
// multiplies by rowinv, writes normalized W back, splits for MMA.
__global__ void __launch_bounds__(512) av_fused(float* Wt)
{
    constexpr int TA = 256 * 40 * 2;      // 20480
    constexpr int TB = 64 * 40 * 2;       // 5120
    constexpr int STAGE = 2 * TA + 2 * TB;
    extern __shared__ char sm[];
    float* sInv = (float*)(sm + 2 * STAGE);
    int t = threadIdx.x, w = t >> 5, lane = t & 31;
    int h = blockIdx.z, m0 = blockIdx.y * 256;
    int wm = w >> 1, wn = w & 1;
    float* Ap = Wt + (long long)h * SS + (long long)m0 * SQ;
    const float* Bp = g_vt + (long long)h * 64 * SQ;

    wmma::fragment<wmma::accumulator, 16, 16, 16, float> acc[2][2];
    #pragma unroll
    for (int i = 0; i < 2; i++)
        #pragma unroll
        for (int j = 0; j < 2; j++) wmma::fill_fragment(acc[i][j], 0.0f);

    float4 xa[4], xb;
    #pragma unroll
    for (int i = 0; i < 4; i++) {
        int idx = t + 512 * i;
        xa[i] = *(const float4*)(Ap + (long long)(idx >> 3) * SQ + (idx & 7) * 4);
    }
    xb = *(const float4*)(Bp + (long long)(t >> 3) * SQ + (t & 7) * 4);
    if (t < 256) sInv[t] = g_rowinv[h * SQ + m0 + t];
    __syncthreads();
    {
        bf16 (*Ah)[40] = (bf16(*)[40])(sm);
        bf16 (*Al)[40] = (bf16(*)[40])(sm + TA);
        bf16 (*Bh)[40] = (bf16(*)[40])(sm + 2 * TA);
        bf16 (*Bl)[40] = (bf16(*)[40])(sm + 2 * TA + TB);
        #pragma unroll
        for (int i = 0; i < 4; i++) {
            int idx = t + 512 * i;
            int r = idx >> 3, c = (idx & 7) * 4;
            float s = sInv[r];
            float4 v = make_float4(xa[i].x * s, xa[i].y * s, xa[i].z * s, xa[i].w * s);
            *(float4*)(Ap + (long long)r * SQ + c) = v;
            st_split(Ah, Al, idx, v, (const float*)0, 0);
        }
        st_split(Bh, Bl, t, xb, (const float*)0, 0);
    }
    __syncthreads();

    int stage = 0;
    for (int k0 = 0; k0 < SQ; k0 += 32) {
        bool nxt = (k0 + 32) < SQ;
        if (nxt) {
            int kn = k0 + 32;
            #pragma unroll
            for (int i = 0; i < 4; i++) {
                int idx = t + 512 * i;
                xa[i] = *(const float4*)(Ap + (long long)(idx >> 3) * SQ + kn + (idx & 7) * 4);
            }
            xb = *(const float4*)(Bp + (long long)(t >> 3) * SQ + kn + (t & 7) * 4);
        }
        {
            bf16 (*Ah)[40] = (bf16(*)[40])(sm + stage * STAGE);
            bf16 (*Al)[40] = (bf16(*)[40])(sm + stage * STAGE + TA);
            bf16 (*Bh)[40] = (bf16(*)[40])(sm + stage * STAGE + 2 * TA);
            bf16 (*Bl)[40] = (bf16(*)[40])(sm + stage * STAGE + 2 * TA + TB);
            #pragma unroll
            for (int kk = 0; kk < 32; kk += 16) {
                wmma::fragment<wmma::matrix_a, 16, 16, 16, bf16, wmma::row_major> ah[2], al[2];
                wmma::fragment<wmma::matrix_b, 16, 16, 16, bf16, wmma::col_major> bh[2], bl[2];
                #pragma unroll
                for (int i = 0; i < 2; i++) {
                    wmma::load_matrix_sync(ah[i], &Ah[wm * 32 + i * 16][kk], 40);
                    wmma::load_matrix_sync(al[i], &Al[wm * 32 + i * 16][kk], 40);
                }
                #pragma unroll
                for (int j = 0; j < 2; j++) {
                    wmma::load_matrix_sync(bh[j], &Bh[wn * 32 + j * 16][kk], 40);
                    wmma::load_matrix_sync(bl[j], &Bl[wn * 32 + j * 16][kk], 40);
                }
                #pragma unroll
                for (int i = 0; i < 2; i++)
                    #pragma unroll
                    for (int j = 0; j < 2; j++) {
                        wmma::mma_sync(acc[i][j], ah[i], bh[j], acc[i][j]);
                        wmma::mma_sync(acc[i][j], ah[i], bl[j], acc[i][j]);
                        wmma::mma_sync(acc[i][j], al[i], bh[j], acc[i][j]);
                    }
            }
        }
        if (nxt) {
            int ns = stage ^ 1;
            bf16 (*Ah)[40] = (bf16(*)[40])(sm + ns * STAGE);
            bf16 (*Al)[40] = (bf16(*)[40])(sm + ns * STAGE + TA);
            bf16 (*Bh)[40] = (bf16(*)[40])(sm + ns * STAGE + 2 * TA);
            bf16 (*Bl)[40] = (bf16(*)[40])(sm + ns * STAGE + 2 * TA + TB);
            int kn = k0 + 32;
            #pragma unroll
            for (int i = 0; i < 4; i++) {
                int idx = t + 512 * i;
                int r = idx >> 3, c = (idx & 7) * 4;
                float s = sInv[r];
                float4 v = make_float4(xa[i].x * s, xa[i].y * s, xa[i].z * s, xa[i].w * s);
                *(float4*)(Ap + (long long)r * SQ + kn + c) = v;
                st_split(Ah, Al, idx, v, (const float*)0, 0);
            }
            st_split(Bh, Bl, t, xb, (const float*)0, 0);
            __syncthreads();
            stage = ns;
        }
    }
    __syncthreads();

    float (*sc)[32][36] = (float(*)[32][36])sm;
    #pragma unroll
    for (int i = 0; i < 2; i++)
        #pragma unroll
        for (int j = 0; j < 2; j++)
            wmma::store_matrix_sync(&sc[w][i * 16][j * 16], acc[i][j], 36, wmma::mem_row_major);
    __syncwarp();

    int cn = wn * 32;
    int m = m0 + wm * 32 + lane;
    const float* srow = sc[w][lane];
    float* cr = g_ctx + (long long)m * DM + h * 64 + cn;
    #pragma unroll
    for (int j = 0; j < 32; j += 4)
        *(float4*)(cr + j) = make_float4(srow[j], srow[j + 1], srow[j + 2], srow[j + 3]);
}

// ---------------- launch ----------------
extern "C" void kernel_launch(void* const* d_in, const int* in_sizes, int n_in,
                              void* d_out, int out_size)
{
    const float* query = (const float*)d_in[0];
    const float* key   = (const float*)d_in[1];
    const float* value = (const float*)d_in[2];
    const float* Wq    = (const float*)d_in[4];
    const float* Wke   = (const float*)d_in[5];
    const float* Wkr   = (const float*)d_in[6];
    const float* Wv    = (const float*)d_in[7];
    const float* Wf    = (const float*)d_in[8];
    const float* u_p   = (const float*)d_in[9];
    const float* v_p   = (const float*)d_in[10];

    float* out  = (float*)d_out;
    float* Wt   = out + (long long)SQ * DM;
    float* loss = Wt + (long long)NH * SS;

    float* fctx;
    cudaGetSymbolAddress((void**)&fctx, g_ctx);

    const int DSM_128_128 = 2 * (2 * 128 * 80 + 2 * 128 * 80);   // 81920
    const int DSM_AV      = 2 * (2 * 256 * 80 + 2 * 64 * 80) + 1024;  // 103424
    cudaFuncSetAttribute(proj4, cudaFuncAttributeMaxDynamicSharedMemorySize, DSM_128_128);
    cudaFuncSetAttribute(wgemm<128, 128>, cudaFuncAttributeMaxDynamicSharedMemorySize, DSM_128_128);
    cudaFuncSetAttribute(av_fused, cudaFuncAttributeMaxDynamicSharedMemorySize, DSM_AV);
    cudaFuncSetAttribute(score_fused, cudaFuncAttributeMaxDynamicSharedMemorySize, SF_TOTAL);

    relenc_kernel<<<(SQ * DM) / 256, 256>>>();

    proj4<<<dim3(DM / 128, SQ / 128, 4), 512, DSM_128_128>>>(
        query, key, value, Wq, Wke, Wv, Wkr);

    // scores -> e = exp(score) + per-(row, f-block) partial sum/max
    score_fused<<<dim3(SQ / 128, SQ / 128, NH), 512, SF_TOTAL>>>(u_p, v_p, Wt);

    stat_kernel<<<(NH * SQ) / 256, 256>>>();

    // av: normalize e by rowinv, write W back, ctx = W @ v
    av_fused<<<dim3(1, SQ / 256, NH), 512, DSM_AV>>>(Wt);

    wgemm<128, 128><<<dim3(DM / 128, SQ / 128, 1), 512, DSM_128_128>>>(
        fctx, Wf, out, DM, DM, DM, DM, 0, 0, 0, 0, 2);

    loss_kernel<<<1, 256>>>(loss);
}

// round 17
// speedup vs baseline: 1.3989x; 1.3376x over previous
#include <cuda_runtime.h>
#include <cuda_bf16.h>
#include <mma.h>
#include <math.h>
#include <stdint.h>

using namespace nvcuda;
typedef __nv_bfloat16 bf16;
static constexpr int SQ = 2048, DM = 1024, NH = 16;
static constexpr long long SS = (long long)SQ * SQ;

__device__ float g_rel[SQ*DM], g_q[SQ*DM], g_k[SQ*DM];
__device__ float g_qrel[SQ*DM], g_vt[DM*SQ], g_ctx[SQ*DM];
__device__ float g_psum[NH*SQ*16], g_pmax[NH*SQ*16];
__device__ float g_rowinv[NH*SQ], g_rowwmax[NH*SQ];
__device__ float g_div[DM/2];

// ---------------- small kernels ----------------
__global__ void divtab_kernel() {
    int i = threadIdx.x + blockIdx.x * 256;   // i indexes even column i2 = 2*i
    if (i >= DM / 2) return;
    double dv = exp(-((double)(2 * i) / (double)DM) * log(10000.0));
    g_div[i] = (float)dv;
}

__global__ void relenc_kernel() {
    int idx = blockIdx.x * blockDim.x + threadIdx.x;
    if (idx >= SQ * DM) return;
    int f = idx >> 10, c = idx & (DM - 1);
    int p = SQ - 1 - f;
    float divf = g_div[c >> 1];
    float angf = (float)p * divf;
    g_rel[idx] = (c & 1) ? cosf(angf) : sinf(angf);
}

// split one float4 into hi/lo bf16 quads; store at pitch-40 layout
__device__ __forceinline__ void st_split(bf16 (*H)[40], bf16 (*L)[40],
    int idx, float4 x, const float* __restrict__ bias, int kcol)
{
    float xv[4] = {x.x, x.y, x.z, x.w};
    if (bias) {
        #pragma unroll
        for (int e = 0; e < 4; e++) xv[e] += bias[kcol + e];
    }
    __align__(8) bf16 h[4], l[4];
    #pragma unroll
    for (int e = 0; e < 4; e++) {
        h[e] = __float2bfloat16(xv[e]);
        l[e] = __float2bfloat16(xv[e] - __bfloat162float(h[e]));
    }
    int r = idx >> 3, c = (idx & 7) * 4;
    *(uint2*)&H[r][c] = *(uint2*)h;
    *(uint2*)&L[r][c] = *(uint2*)l;
}

// ---------------- split-bf16 WMMA GEMM body: 512 threads, 16 warps --------
template <int BM, int BN>
__device__ __forceinline__ void wgemm_body(char* sm,
    const float* __restrict__ A, const float* __restrict__ B, float* __restrict__ C,
    int K, int lda, int ldb, int ldc, const float* __restrict__ bp,
    int m0, int n0, int mode)
{
    constexpr int NWN = BN / 32;
    constexpr int NWM = 16 / NWN;
    constexpr int FM  = BM / (NWM * 16);
    constexpr int TA  = BM * 40 * 2;
    constexpr int TB  = BN * 40 * 2;
    constexpr int STAGE = 2 * TA + 2 * TB;
    constexpr int NA4 = BM / 64;
    constexpr int NB4 = BN / 64 > 0 ? BN / 64 : 1;

    int t = threadIdx.x, w = t >> 5, lane = t & 31;
    int wm = w / NWN, wn = w % NWN;
    const float* Ap = A + (long long)m0 * lda;
    const float* Bp = B + (long long)n0 * ldb;

    wmma::fragment<wmma::accumulator, 16, 16, 16, float> acc[FM][2];
    #pragma unroll
    for (int i = 0; i < FM; i++)
        #pragma unroll
        for (int j = 0; j < 2; j++) wmma::fill_fragment(acc[i][j], 0.0f);

    float4 xa[NA4], xb[NB4];
    #pragma unroll
    for (int i = 0; i < NA4; i++) {
        int idx = t + 512 * i;
        xa[i] = *(const float4*)(Ap + (long long)(idx >> 3) * lda + (idx & 7) * 4);
    }
    #pragma unroll
    for (int i = 0; i < NB4; i++) {
        int idx = t + 512 * i;
        xb[i] = *(const float4*)(Bp + (long long)(idx >> 3) * ldb + (idx & 7) * 4);
    }
    {
        bf16 (*Ah)[40] = (bf16(*)[40])(sm);
        bf16 (*Al)[40] = (bf16(*)[40])(sm + TA);
        bf16 (*Bh)[40] = (bf16(*)[40])(sm + 2 * TA);
        bf16 (*Bl)[40] = (bf16(*)[40])(sm + 2 * TA + TB);
        #pragma unroll
        for (int i = 0; i < NA4; i++) {
            int idx = t + 512 * i;
            st_split(Ah, Al, idx, xa[i], bp, (idx & 7) * 4);
        }
        #pragma unroll
        for (int i = 0; i < NB4; i++) {
            int idx = t + 512 * i;
            st_split(Bh, Bl, idx, xb[i], (const float*)0, 0);
        }
    }
    __syncthreads();

    int stage = 0;
    for (int k0 = 0; k0 < K; k0 += 32) {
        bool nxt = (k0 + 32) < K;
        if (nxt) {
            int kn = k0 + 32;
            #pragma unroll
            for (int i = 0; i < NA4; i++) {
                int idx = t + 512 * i;
                xa[i] = *(const float4*)(Ap + (long long)(idx >> 3) * lda + kn + (idx & 7) * 4);
            }
            #pragma unroll
            for (int i = 0; i < NB4; i++) {
                int idx = t + 512 * i;
                xb[i] = *(const float4*)(Bp + (long long)(idx >> 3) * ldb + kn + (idx & 7) * 4);
            }
        }
        {
            bf16 (*Ah)[40] = (bf16(*)[40])(sm + stage * STAGE);
            bf16 (*Al)[40] = (bf16(*)[40])(sm + stage * STAGE + TA);
            bf16 (*Bh)[40] = (bf16(*)[40])(sm + stage * STAGE + 2 * TA);
            bf16 (*Bl)[40] = (bf16(*)[40])(sm + stage * STAGE + 2 * TA + TB);
            #pragma unroll
            for (int kk = 0; kk < 32; kk += 16) {
                wmma::fragment<wmma::matrix_a, 16, 16, 16, bf16, wmma::row_major> ah[FM], al[FM];
                wmma::fragment<wmma::matrix_b, 16, 16, 16, bf16, wmma::col_major> bh[2], bl[2];
                #pragma unroll
                for (int i = 0; i < FM; i++) {
                    wmma::load_matrix_sync(ah[i], &Ah[wm * 32 + i * 16][kk], 40);
                    wmma::load_matrix_sync(al[i], &Al[wm * 32 + i * 16][kk], 40);
                }
                #pragma unroll
                for (int j = 0; j < 2; j++) {
                    wmma::load_matrix_sync(bh[j], &Bh[wn * 32 + j * 16][kk], 40);
                    wmma::load_matrix_sync(bl[j], &Bl[wn * 32 + j * 16][kk], 40);
                }
                #pragma unroll
                for (int i = 0; i < FM; i++)
                    #pragma unroll
                    for (int j = 0; j < 2; j++) {
                        wmma::mma_sync(acc[i][j], ah[i], bh[j], acc[i][j]);
                        wmma::mma_sync(acc[i][j], ah[i], bl[j], acc[i][j]);
                        wmma::mma_sync(acc[i][j], al[i], bh[j], acc[i][j]);
                    }
            }
        }
        if (nxt) {
            int ns = stage ^ 1;
            bf16 (*Ah)[40] = (bf16(*)[40])(sm + ns * STAGE);
            bf16 (*Al)[40] = (bf16(*)[40])(sm + ns * STAGE + TA);
            bf16 (*Bh)[40] = (bf16(*)[40])(sm + ns * STAGE + 2 * TA);
            bf16 (*Bl)[40] = (bf16(*)[40])(sm + ns * STAGE + 2 * TA + TB);
            int kn = k0 + 32;
            #pragma unroll
            for (int i = 0; i < NA4; i++) {
                int idx = t + 512 * i;
                st_split(Ah, Al, idx, xa[i], bp, kn + (idx & 7) * 4);
            }
            #pragma unroll
            for (int i = 0; i < NB4; i++) {
                int idx = t + 512 * i;
                st_split(Bh, Bl, idx, xb[i], (const float*)0, 0);
            }
            __syncthreads();
            stage = ns;
        }
    }
    __syncthreads();

    float (*sc)[32][36] = (float(*)[32][36])sm;
    #pragma unroll
    for (int i = 0; i < FM; i++)
        #pragma unroll
        for (int j = 0; j < 2; j++)
            wmma::store_matrix_sync(&sc[w][i * 16][j * 16], acc[i][j], 36, wmma::mem_row_major);
    __syncwarp();

    int cn = n0 + wn * 32;
    int m = m0 + wm * 32 + lane;
    const float* srow = sc[w][lane];
    if (mode == 0) {
        float* cr = C + (long long)m * ldc + cn;
        #pragma unroll
        for (int j = 0; j < 32; j += 4)
            *(float4*)(cr + j) = make_float4(srow[j], srow[j + 1], srow[j + 2], srow[j + 3]);
    } else if (mode == 2) {
        float* cr = C + (long long)m * ldc + cn;
        #pragma unroll
        for (int j = 0; j < 32; j += 4) {
            float4 r;
            float x0 = srow[j], x1 = srow[j + 1], x2 = srow[j + 2], x3 = srow[j + 3];
            r.x = 0.5f * x0 * (1.0f + erff(x0 * 0.70710678f));
            r.y = 0.5f * x1 * (1.0f + erff(x1 * 0.70710678f));
            r.z = 0.5f * x2 * (1.0f + erff(x2 * 0.70710678f));
            r.w = 0.5f * x3 * (1.0f + erff(x3 * 0.70710678f));
            *(float4*)(cr + j) = r;
        }
    } else {   // mode 3: transposed store into [DM][SQ] (vt)
        #pragma unroll
        for (int j = 0; j < 32; j++)
            C[(long long)(cn + j) * SQ + m] = srow[j];
    }
}

template <int BM, int BN>
__global__ void __launch_bounds__(512) wgemm(
    const float* __restrict__ A, const float* __restrict__ B, float* __restrict__ C,
    int K, int lda, int ldb, int ldc, long long aZ, long long bZ, long long cZ,
    const float* __restrict__ bias, int mode)
{
    extern __shared__ char sm[];
    int z = blockIdx.z;
    wgemm_body<BM, BN>(sm,
        A + (long long)z * aZ, B + (long long)z * bZ, C + (long long)z * cZ,
        K, lda, ldb, ldc, bias ? bias + (long long)z * 64 : (const float*)0,
        blockIdx.y * BM, blockIdx.x * BN, mode);
}

// all 4 projections in one launch; z==2 (value) writes g_vt transposed
__global__ void __launch_bounds__(512) proj4(
    const float* __restrict__ query, const float* __restrict__ key,
    const float* __restrict__ value,
    const float* __restrict__ Wq, const float* __restrict__ Wke,
    const float* __restrict__ Wv, const float* __restrict__ Wkr)
{
    extern __shared__ char sm[];
    const float* A; const float* B; float* C; int mode = 0;
    switch (blockIdx.z) {
        case 0:  A = query; B = Wq;  C = g_q;    break;
        case 1:  A = key;   B = Wke; C = g_k;    break;
        case 2:  A = value; B = Wv;  C = g_vt; mode = 3; break;
        default: A = g_rel; B = Wkr; C = g_qrel; break;
    }
    wgemm_body<128, 128>(sm, A, B, C, DM, DM, DM, DM, (const float*)0,
                         blockIdx.y * 128, blockIdx.x * 128, mode);
}

// ---------------- fused score kernel (+ exp + row partials) ---------------
static constexpr int SF_QV_H = 0;
static constexpr int SF_QV_L = 18432;
static constexpr int SF_QR_H = 36864;
static constexpr int SF_QR_L = 73728;
static constexpr int SF_P    = 0;
static constexpr int SF_B    = 137216;
static constexpr int SF_SC   = 137216;
static constexpr int SF_E    = 210944;
static constexpr int SF_QL   = 211968;
static constexpr int SF_TOTAL = 212224;

__device__ __forceinline__ void split64(bf16 (*H)[72], bf16 (*L)[72],
    int r, int q, float4 x, const float* __restrict__ bias)
{
    float xv[4] = {x.x, x.y, x.z, x.w};
    if (bias) {
        #pragma unroll
        for (int e = 0; e < 4; e++) xv[e] += bias[q * 4 + e];
    }
    __align__(8) bf16 h[4], l[4];
    #pragma unroll
    for (int e = 0; e < 4; e++) {
        h[e] = __float2bfloat16(xv[e]);
        l[e] = __float2bfloat16(xv[e] - __bfloat162float(h[e]));
    }
    *(uint2*)&H[r][q * 4] = *(uint2*)h;
    *(uint2*)&L[r][q * 4] = *(uint2*)l;
}

__global__ void __launch_bounds__(512) score_fused(
    const float* __restrict__ u_p, const float* __restrict__ v_p,
    float* __restrict__ Wout)
{
    extern __shared__ char sm[];
    int t = threadIdx.x, w = t >> 5;
    int f0 = blockIdx.x * 128, s0 = blockIdx.y * 128, h = blockIdx.z;
    int g0 = f0 - s0;
    int n1 = min(g0 + 127, 0) - g0 + 128; if (n1 < 0) n1 = 0;
    int gBmin = max(g0 - 127, 2);
    int n2 = g0 + 127 - gBmin + 1; if (n2 < 0) n2 = 0;
    const float* uq = u_p + h * 64;
    const float* vq = v_p + h * 64;
    bool needE = (g0 >= 128);

    bf16 (*qvH)[72] = (bf16(*)[72])(sm + SF_QV_H);
    bf16 (*qvL)[72] = (bf16(*)[72])(sm + SF_QV_L);
    bf16 (*qrH)[72] = (bf16(*)[72])(sm + SF_QR_H);
    bf16 (*qrL)[72] = (bf16(*)[72])(sm + SF_QR_L);
    bf16 (*quH)[72] = (bf16(*)[72])(sm + SF_B);
    bf16 (*quL)[72] = (bf16(*)[72])(sm + SF_B + 18432);
    bf16 (*kH)[72]  = (bf16(*)[72])(sm + SF_B + 36864);
    bf16 (*kL)[72]  = (bf16(*)[72])(sm + SF_B + 55296);
    float* Ebuf = (float*)(sm + SF_E);
    float* qlS  = (float*)(sm + SF_QL);

    #pragma unroll
    for (int i = 0; i < 4; i++) {
        int idx = t + 512 * i;
        int r = idx >> 4, q = idx & 15;
        float4 x = *(const float4*)(g_q + (long long)(s0 + r) * DM + h * 64 + q * 4);
        split64(qvH, qvL, r, q, x, vq);
    }
    #pragma unroll
    for (int i = 0; i < 8; i++) {
        int idx = t + 512 * i;
        int r = idx >> 4, q = idx & 15;
        int wr = (r < n1) ? (1920 + g0 + r) : ((r - n1 < n2) ? (gBmin - 2 + (r - n1)) : 0);
        float4 x = *(const float4*)(g_qrel + (long long)wr * DM + h * 64 + q * 4);
        split64(qrH, qrL, r, q, x, (const float*)0);
    }
    #pragma unroll
    for (int i = 0; i < 4; i++) {
        int idx = t + 512 * i;
        int r = idx >> 4, q = idx & 15;
        float4 x = *(const float4*)(g_q + (long long)(s0 + r) * DM + h * 64 + q * 4);
        split64(quH, quL, r, q, x, uq);
    }
    #pragma unroll
    for (int i = 0; i < 4; i++) {
        int idx = t + 512 * i;
        int r = idx >> 4, q = idx & 15;
        float4 x = *(const float4*)(g_k + (long long)(f0 + r) * DM + h * 64 + q * 4);
        split64(kH, kL, r, q, x, (const float*)0);
    }
    if (needE && t < 64)
        qlS[t] = g_q[(long long)(s0 + 128) * DM + h * 64 + t] + vq[t];
    __syncthreads();

    int wm = w >> 2, wn = w & 3;
    {
        wmma::fragment<wmma::accumulator, 16, 16, 16, float> accP[2][4];
        #pragma unroll
        for (int i = 0; i < 2; i++)
            #pragma unroll
            for (int n = 0; n < 4; n++) wmma::fill_fragment(accP[i][n], 0.0f);
        #pragma unroll
        for (int k4 = 0; k4 < 4; k4++) {
            // hoisted A-fragment loads (once per k4, reused across all n)
            wmma::fragment<wmma::matrix_a, 16, 16, 16, bf16, wmma::row_major> ah[2], al[2];
            #pragma unroll
            for (int i = 0; i < 2; i++) {
                wmma::load_matrix_sync(ah[i], &qvH[wm * 32 + i * 16][k4 * 16], 72);
                wmma::load_matrix_sync(al[i], &qvL[wm * 32 + i * 16][k4 * 16], 72);
            }
            #pragma unroll
            for (int n = 0; n < 4; n++) {
                wmma::fragment<wmma::matrix_b, 16, 16, 16, bf16, wmma::col_major> bh, bl;
                wmma::load_matrix_sync(bh, &qrH[wn * 64 + n * 16][k4 * 16], 72);
                wmma::load_matrix_sync(bl, &qrL[wn * 64 + n * 16][k4 * 16], 72);
                #pragma unroll
                for (int i = 0; i < 2; i++) {
                    wmma::mma_sync(accP[i][n], ah[i], bh, accP[i][n]);
                    wmma::mma_sync(accP[i][n], ah[i], bl, accP[i][n]);
                    wmma::mma_sync(accP[i][n], al[i], bh, accP[i][n]);
                }
            }
        }
        if (needE && t < 256 && t < n1 + n2) {
            float a = 0.0f;
            #pragma unroll 8
            for (int k = 0; k < 64; k++)
                a += qlS[k] * (__bfloat162float(qrH[t][k]) + __bfloat162float(qrL[t][k]));
            Ebuf[t] = a;
        }
        __syncthreads();
        float (*P)[268] = (float(*)[268])(sm + SF_P);
        #pragma unroll
        for (int i = 0; i < 2; i++)
            #pragma unroll
            for (int n = 0; n < 4; n++)
                wmma::store_matrix_sync(&P[wm * 32 + i * 16][wn * 64 + n * 16],
                                        accP[i][n], 268, wmma::mem_row_major);
    }

    wmma::fragment<wmma::accumulator, 16, 16, 16, float> acc2[2][2];
    #pragma unroll
    for (int i = 0; i < 2; i++)
        #pragma unroll
        for (int n = 0; n < 2; n++) wmma::fill_fragment(acc2[i][n], 0.0f);
    #pragma unroll
    for (int k4 = 0; k4 < 4; k4++) {
        wmma::fragment<wmma::matrix_a, 16, 16, 16, bf16, wmma::row_major> ah[2], al[2];
        #pragma unroll
        for (int i = 0; i < 2; i++) {
            wmma::load_matrix_sync(ah[i], &quH[wm * 32 + i * 16][k4 * 16], 72);
            wmma::load_matrix_sync(al[i], &quL[wm * 32 + i * 16][k4 * 16], 72);
        }
        #pragma unroll
        for (int n = 0; n < 2; n++) {
            wmma::fragment<wmma::matrix_b, 16, 16, 16, bf16, wmma::col_major> bh, bl;
            wmma::load_matrix_sync(bh, &kH[wn * 32 + n * 16][k4 * 16], 72);
            wmma::load_matrix_sync(bl, &kL[wn * 32 + n * 16][k4 * 16], 72);
            #pragma unroll
            for (int i = 0; i < 2; i++) {
                wmma::mma_sync(acc2[i][n], ah[i], bh, acc2[i][n]);
                wmma::mma_sync(acc2[i][n], ah[i], bl, acc2[i][n]);
                wmma::mma_sync(acc2[i][n], al[i], bh, acc2[i][n]);
            }
        }
    }
    __syncthreads();
    float (*scr)[32][36] = (float(*)[32][36])(sm + SF_SC);
    #pragma unroll
    for (int i = 0; i < 2; i++)
        #pragma unroll
        for (int n = 0; n < 2; n++)
            wmma::store_matrix_sync(&scr[w][i * 16][n * 16], acc2[i][n], 36,
                                    wmma::mem_row_major);
    __syncthreads();

    // epilogue: BD gather, scale, e = exp, store + row partial sum/max
    {
        float (*P)[268] = (float(*)[268])(sm + SF_P);
        int row = t >> 2, cs = (t & 3) * 32;
        int s = s0 + row;
        const float* srow = scr[(row >> 5) * 4 + (t & 3)][row & 31];
        float* co = Wout + (long long)h * SS + (long long)s * SQ + f0 + cs;
        float tsum = 0.0f, tmax = 0.0f;
        #pragma unroll
        for (int j0 = 0; j0 < 32; j0 += 4) {
            float o[4];
            #pragma unroll
            for (int e = 0; e < 4; e++) {
                int j = j0 + e;
                int f = f0 + cs + j;
                int g = f - s;
                float bd;
                if (g <= 0)       bd = P[row][g - g0 + 127];
                else if (g == 1)  bd = 0.0f;
                else {
                    int jj = n1 + g - gBmin;
                    bd = (row < 127) ? P[row + 1][jj] : Ebuf[jj];
                }
                float sc_ = (srow[j] + bd) * 0.03125f;
                float ev = __expf(sc_);
                o[e] = ev;
                tsum += ev;
                tmax = fmaxf(tmax, ev);
            }
            *(float4*)(co + j0) = make_float4(o[0], o[1], o[2], o[3]);
        }
        tsum += __shfl_xor_sync(0xffffffffu, tsum, 1);
        tsum += __shfl_xor_sync(0xffffffffu, tsum, 2);
        tmax = fmaxf(tmax, __shfl_xor_sync(0xffffffffu, tmax, 1));
        tmax = fmaxf(tmax, __shfl_xor_sync(0xffffffffu, tmax, 2));
        if ((t & 3) == 0) {
            int ridx = (((h * SQ) + s) << 4) + blockIdx.x;
            g_psum[ridx] = tsum;
            g_pmax[ridx] = tmax;
        }
    }
}

// ---------------- row stats + loss ----------------
__global__ void stat_kernel() {
    int idx = blockIdx.x * 256 + threadIdx.x;
    if (idx >= NH * SQ) return;
    const float* ps = g_psum + ((long long)idx << 4);
    const float* pm = g_pmax + ((long long)idx << 4);
    float s = 0.0f, m = 0.0f;
    #pragma unroll
    for (int i = 0; i < 16; i++) { s += ps[i]; m = fmaxf(m, pm[i]); }
    float inv = 1.0f / s;
    g_rowinv[idx]  = inv;
    g_rowwmax[idx] = m * inv;
}

__global__ void __launch_bounds__(256) loss_kernel(float* __restrict__ loss) {
    __shared__ float red[8];
    int t = threadIdx.x, lane = t & 31, wid = t >> 5;
    float total = 0.0f;
    for (int h = 0; h < NH; h++) {
        float m = 0.0f;
        for (int r = t; r < SQ; r += 256) m = fmaxf(m, g_rowwmax[h * SQ + r]);
        #pragma unroll
        for (int o = 16; o > 0; o >>= 1) m = fmaxf(m, __shfl_xor_sync(0xffffffffu, m, o));
        if (lane == 0) red[wid] = m;
        __syncthreads();
        if (t == 0) {
            float M = red[0];
            #pragma unroll
            for (int i = 1; i < 8; i++) M = fmaxf(M, red[i]);
            total += M;
        }
        __syncthreads();
    }
    if (t == 0) loss[0] = total / (float)NH;
}

// ---------------- av with fused normalization + W writeback ---------------
__global__ void __launch_bounds__(512) av_fused(float* Wt)
{
    constexpr int TA = 256 * 40 * 2;
    constexpr int TB = 64 * 40 * 2;
    constexpr int STAGE = 2 * TA + 2 * TB;
    extern __shared__ char sm[];
    float* sInv = (float*)(sm + 2 * STAGE);
    int t = threadIdx.x, w = t >> 5, lane = t & 31;
    int h = blockIdx.z, m0 = blockIdx.y * 256;
    int wm = w >> 1, wn = w & 1;
    float* Ap = Wt + (long long)h * SS + (long long)m0 * SQ;
    const float* Bp = g_vt + (long long)h * 64 * SQ;

    wmma::fragment<wmma::accumulator, 16, 16, 16, float> acc[2][2];
    #pragma unroll
    for (int i = 0; i < 2; i++)
        #pragma unroll
        for (int j = 0; j < 2; j++) wmma::fill_fragment(acc[i][j], 0.0f);

    float4 xa[4], xb;
    #pragma unroll
    for (int i = 0; i < 4; i++) {
        int idx = t + 512 * i;
        xa[i] = *(const float4*)(Ap + (long long)(idx >> 3) * SQ + (idx & 7) * 4);
    }
    xb = *(const float4*)(Bp + (long long)(t >> 3) * SQ + (t & 7) * 4);
    if (t < 256) sInv[t] = g_rowinv[h * SQ + m0 + t];
    __syncthreads();
    {
        bf16 (*Ah)[40] = (bf16(*)[40])(sm);
        bf16 (*Al)[40] = (bf16(*)[40])(sm + TA);
        bf16 (*Bh)[40] = (bf16(*)[40])(sm + 2 * TA);
        bf16 (*Bl)[40] = (bf16(*)[40])(sm + 2 * TA + TB);
        #pragma unroll
        for (int i = 0; i < 4; i++) {
            int idx = t + 512 * i;
            int r = idx >> 3, c = (idx & 7) * 4;
            float s = sInv[r];
            float4 v = make_float4(xa[i].x * s, xa[i].y * s, xa[i].z * s, xa[i].w * s);
            *(float4*)(Ap + (long long)r * SQ + c) = v;
            st_split(Ah, Al, idx, v, (const float*)0, 0);
        }
        st_split(Bh, Bl, t, xb, (const float*)0, 0);
    }
    __syncthreads();

    int stage = 0;
    for (int k0 = 0; k0 < SQ; k0 += 32) {
        bool nxt = (k0 + 32) < SQ;
        if (nxt) {
            int kn = k0 + 32;
            #pragma unroll
            for (int i = 0; i < 4; i++) {
                int idx = t + 512 * i;
                xa[i] = *(const float4*)(Ap + (long long)(idx >> 3) * SQ + kn + (idx & 7) * 4);
            }
            xb = *(const float4*)(Bp + (long long)(t >> 3) * SQ + kn + (t & 7) * 4);
        }
        {
            bf16 (*Ah)[40] = (bf16(*)[40])(sm + stage * STAGE);
            bf16 (*Al)[40] = (bf16(*)[40])(sm + stage * STAGE + TA);
            bf16 (*Bh)[40] = (bf16(*)[40])(sm + stage * STAGE + 2 * TA);
            bf16 (*Bl)[40] = (bf16(*)[40])(sm + stage * STAGE + 2 * TA + TB);
            #pragma unroll
            for (int kk = 0; kk < 32; kk += 16) {
                wmma::fragment<wmma::matrix_a, 16, 16, 16, bf16, wmma::row_major> ah[2], al[2];
                wmma::fragment<wmma::matrix_b, 16, 16, 16, bf16, wmma::col_major> bh[2], bl[2];
                #pragma unroll
                for (int i = 0; i < 2; i++) {
                    wmma::load_matrix_sync(ah[i], &Ah[wm * 32 + i * 16][kk], 40);
                    wmma::load_matrix_sync(al[i], &Al[wm * 32 + i * 16][kk], 40);
                }
                #pragma unroll
                for (int j = 0; j < 2; j++) {
                    wmma::load_matrix_sync(bh[j], &Bh[wn * 32 + j * 16][kk], 40);
                    wmma::load_matrix_sync(bl[j], &Bl[wn * 32 + j * 16][kk], 40);
                }
                #pragma unroll
                for (int i = 0; i < 2; i++)
                    #pragma unroll
                    for (int j = 0; j < 2; j++) {
                        wmma::mma_sync(acc[i][j], ah[i], bh[j], acc[i][j]);
                        wmma::mma_sync(acc[i][j], ah[i], bl[j], acc[i][j]);
                        wmma::mma_sync(acc[i][j], al[i], bh[j], acc[i][j]);
                    }
            }
        }
        if (nxt) {
            int ns = stage ^ 1;
            bf16 (*Ah)[40] = (bf16(*)[40])(sm + ns * STAGE);
            bf16 (*Al)[40] = (bf16(*)[40])(sm + ns * STAGE + TA);
            bf16 (*Bh)[40] = (bf16(*)[40])(sm + ns * STAGE + 2 * TA);
            bf16 (*Bl)[40] = (bf16(*)[40])(sm + ns * STAGE + 2 * TA + TB);
            int kn = k0 + 32;
            #pragma unroll
            for (int i = 0; i < 4; i++) {
                int idx = t + 512 * i;
                int r = idx >> 3, c = (idx & 7) * 4;
                float s = sInv[r];
                float4 v = make_float4(xa[i].x * s, xa[i].y * s, xa[i].z * s, xa[i].w * s);
                *(float4*)(Ap + (long long)r * SQ + kn + c) = v;
                st_split(Ah, Al, idx, v, (const float*)0, 0);
            }
            st_split(Bh, Bl, t, xb, (const float*)0, 0);
            __syncthreads();
            stage = ns;
        }
    }
    __syncthreads();

    float (*sc)[32][36] = (float(*)[32][36])sm;
    #pragma unroll
    for (int i = 0; i < 2; i++)
        #pragma unroll
        for (int j = 0; j < 2; j++)
            wmma::store_matrix_sync(&sc[w][i * 16][j * 16], acc[i][j], 36, wmma::mem_row_major);
    __syncwarp();

    int cn = wn * 32;
    int m = m0 + wm * 32 + lane;
    const float* srow = sc[w][lane];
    float* cr = g_ctx + (long long)m * DM + h * 64 + cn;
    #pragma unroll
    for (int j = 0; j < 32; j += 4)
        *(float4*)(cr + j) = make_float4(srow[j], srow[j + 1], srow[j + 2], srow[j + 3]);
}

// ---------------- launch ----------------
extern "C" void kernel_launch(void* const* d_in, const int* in_sizes, int n_in,
                              void* d_out, int out_size)
{
    const float* query = (const float*)d_in[0];
    const float* key   = (const float*)d_in[1];
    const float* value = (const float*)d_in[2];
    const float* Wq    = (const float*)d_in[4];
    const float* Wke   = (const float*)d_in[5];
    const float* Wkr   = (const float*)d_in[6];
    const float* Wv    = (const float*)d_in[7];
    const float* Wf    = (const float*)d_in[8];
    const float* u_p   = (const float*)d_in[9];
    const float* v_p   = (const float*)d_in[10];

    float* out  = (float*)d_out;
    float* Wt   = out + (long long)SQ * DM;
    float* loss = Wt + (long long)NH * SS;

    float* fctx;
    cudaGetSymbolAddress((void**)&fctx, g_ctx);

    const int DSM_128_128 = 2 * (2 * 128 * 80 + 2 * 128 * 80);        // 81920
    const int DSM_AV      = 2 * (2 * 256 * 80 + 2 * 64 * 80) + 1024;  // 103424
    cudaFuncSetAttribute(proj4, cudaFuncAttributeMaxDynamicSharedMemorySize, DSM_128_128);
    cudaFuncSetAttribute(wgemm<128, 128>, cudaFuncAttributeMaxDynamicSharedMemorySize, DSM_128_128);
    cudaFuncSetAttribute(av_fused, cudaFuncAttributeMaxDynamicSharedMemorySize, DSM_AV);
    cudaFuncSetAttribute(score_fused, cudaFuncAttributeMaxDynamicSharedMemorySize, SF_TOTAL);

    divtab_kernel<<<2, 256>>>();
    relenc_kernel<<<(SQ * DM) / 256, 256>>>();

    proj4<<<dim3(DM / 128, SQ / 128, 4), 512, DSM_128_128>>>(
        query, key, value, Wq, Wke, Wv, Wkr);

    score_fused<<<dim3(SQ / 128, SQ / 128, NH), 512, SF_TOTAL>>>(u_p, v_p, Wt);

    stat_kernel<<<(NH * SQ) / 256, 256>>>();

    av_fused<<<dim3(1, SQ / 256, NH), 512, DSM_AV>>>(Wt);

    wgemm<128, 128><<<dim3(DM / 128, SQ / 128, 1), 512, DSM_128_128>>>(
        fctx, Wf, out, DM, DM, DM, DM, 0, 0, 0, 0, 2);

    loss_kernel<<<1, 256>>>(loss);
}